// round 9
// baseline (speedup 1.0000x reference)
#include <cuda_runtime.h>
#include <cuda_fp16.h>
#include <cuda_bf16.h>
#include <cstdint>

#define NODES_MAX 50000
#define EDGES_MAX 1600000
#define H 256
#define D_IN 518
#define D_INP 544
#define D_OUT 128

#define ZPAD 264              // halves per Z row (256 + 8)
#define BPAD 40               // halves per B row (32 + 8)
#define FUSED_SMEM ((128 * ZPAD + 2 * 128 * BPAD) * 2)   // 88064 bytes

// ---------------- device scratch ----------------
__device__ __half g_h16 [NODES_MAX * H];
__device__ __half g_hwA [NODES_MAX * H];
__device__ __half g_w16 [H * D_INP + 4 * H * H];
__device__ float  g_dis[NODES_MAX];
__device__ int    g_deg[NODES_MAX];
__device__ int    g_start[NODES_MAX + 1];
__device__ int    g_cursor[NODES_MAX];
__device__ int    g_csr_src[EDGES_MAX];
__device__ int    g_bsum[64];
__device__ int    g_boff[64];
__device__ float  g_mean[H];

// ---------------- weight transpose + fp16 ----------------
__global__ void wtrans_kernel(const float* __restrict__ W, __half* __restrict__ WT,
                              int K, int M, int Kp) {
    int idx = blockIdx.x * blockDim.x + threadIdx.x;
    if (idx >= M * Kp) return;
    int m = idx / Kp, k = idx % Kp;
    float v = (k < K) ? W[(size_t)k * M + m] : 0.0f;
    WT[idx] = __float2half_rn(v);
}

// ---------------- degree / normalization ----------------
__global__ void deg_kernel(const int* __restrict__ dst, int* __restrict__ deg, int E) {
    int i = blockIdx.x * blockDim.x + threadIdx.x;
    if (i < E) atomicAdd(&deg[dst[i]], 1);
}

__global__ void dis_kernel(const int* __restrict__ deg, float* __restrict__ dis, int n) {
    int i = blockIdx.x * blockDim.x + threadIdx.x;
    if (i < n) dis[i] = rsqrtf(1.0f + (float)deg[i]);
}

// ---------------- parallel scan (3 phases) ----------------
__global__ void scan_block_kernel(const int* __restrict__ deg, int* __restrict__ start,
                                  int* __restrict__ bsum, int n)
{
    __shared__ int warpSums[32];
    int i = blockIdx.x * 1024 + threadIdx.x;
    int lane = threadIdx.x & 31, warp = threadIdx.x >> 5;
    int v = (i < n) ? deg[i] : 0;
    int inc = v;
#pragma unroll
    for (int off = 1; off < 32; off <<= 1) {
        int t = __shfl_up_sync(0xffffffff, inc, off);
        if (lane >= off) inc += t;
    }
    if (lane == 31) warpSums[warp] = inc;
    __syncthreads();
    if (warp == 0) {
        int s = warpSums[lane];
#pragma unroll
        for (int off = 1; off < 32; off <<= 1) {
            int t = __shfl_up_sync(0xffffffff, s, off);
            if (lane >= off) s += t;
        }
        warpSums[lane] = s;
    }
    __syncthreads();
    int add = (warp > 0) ? warpSums[warp - 1] : 0;
    inc += add;
    if (i < n) start[i + 1] = inc;
    if (threadIdx.x == 1023) bsum[blockIdx.x] = inc;
}

__global__ void scan_sums_kernel(const int* __restrict__ bsum, int* __restrict__ boff, int nb) {
    int lane = threadIdx.x;
    int v = (lane < nb) ? bsum[lane] : 0;
    __shared__ int s[64];
    s[lane] = v;
    __syncthreads();
    for (int off = 1; off < 64; off <<= 1) {
        int t = (lane >= off) ? s[lane - off] : 0;
        __syncthreads();
        s[lane] += t;
        __syncthreads();
    }
    if (lane < nb) boff[lane] = (lane > 0) ? s[lane - 1] : 0;
}

__global__ void scan_finalize_kernel(const int* __restrict__ deg, int* __restrict__ start,
                                     const int* __restrict__ boff, int* __restrict__ cursor, int n)
{
    int i = blockIdx.x * blockDim.x + threadIdx.x;
    if (i < n) {
        int s = start[i + 1] + boff[i >> 10];
        start[i + 1] = s;
        cursor[i] = s - deg[i];
        if (i == 0) start[0] = 0;
    }
}

__global__ void fill_csr_kernel(const int* __restrict__ src, const int* __restrict__ dst,
                                int* __restrict__ cursor, int* __restrict__ csr_src, int E)
{
    int e = blockIdx.x * blockDim.x + threadIdx.x;
    if (e < E) {
        int d = dst[e];
        int p = atomicAdd(&cursor[d], 1);
        csr_src[p] = src[e];
    }
}

// ---------------- enc1: fp32-A x fp16-B GEMM (8B A loads), relu ----------------
__global__ __launch_bounds__(256)
void enc1_gemm_kernel(const float* __restrict__ A, const __half* __restrict__ BT,
                      const float* __restrict__ bias, __half* __restrict__ C16,
                      int N, int K, int Kp, int M)
{
    const int BM = 128, BN = 128, BK = 16, PK = 20, PB = 24;
    __shared__ float As[2][BM][PK];
    __shared__ alignas(16) __half Bh[2][BN][PB];

    int tid = threadIdx.x;
    int wid = tid >> 5, lane = tid & 31;
    int warp_m = (wid & 1) * 64;
    int warp_n = (wid >> 1) * 32;
    int lq = lane & 3;
    int lg = lane >> 2;

    int row0 = blockIdx.y * BM;
    int col0 = blockIdx.x * BN;
    int nt = Kp / BK;

    float c[4][4][4];
#pragma unroll
    for (int mi = 0; mi < 4; mi++)
#pragma unroll
        for (int ni = 0; ni < 4; ni++)
#pragma unroll
            for (int r = 0; r < 4; r++) c[mi][ni][r] = 0.0f;

    int bRow = tid >> 1;
    int bCol = (tid & 1) * 8;

    auto loadTile = [&](int t, int buf) {
        int k0 = t * BK;
#pragma unroll
        for (int it = 0; it < 4; ++it) {
            int idx = it * 256 + tid;             // 1024 chunks of 8B
            int m = idx >> 3, kp = (idx & 7) * 2;
            int gm = row0 + m, gk = k0 + kp;
            const float* src = A + (size_t)gm * K + gk;
            uint32_t dsh = (uint32_t)__cvta_generic_to_shared(&As[buf][m][kp]);
            int sz = (gm < N && gk < K) ? 8 : 0;  // K even -> pair fully in range
            asm volatile("cp.async.ca.shared.global [%0], [%1], 8, %2;"
                         :: "r"(dsh), "l"(src), "r"(sz));
        }
        {
            const __half* src = BT + (size_t)(col0 + bRow) * Kp + k0 + bCol;
            uint32_t dsh = (uint32_t)__cvta_generic_to_shared(&Bh[buf][bRow][bCol]);
            asm volatile("cp.async.cg.shared.global [%0], [%1], 16;"
                         :: "r"(dsh), "l"(src));
        }
        asm volatile("cp.async.commit_group;");
    };

    loadTile(0, 0);
    for (int t = 0; t < nt; ++t) {
        int buf = t & 1;
        if (t + 1 < nt) {
            loadTile(t + 1, (t + 1) & 1);
            asm volatile("cp.async.wait_group 1;");
        } else {
            asm volatile("cp.async.wait_group 0;");
        }
        __syncthreads();

        int kc = lq * 2;
        uint32_t af[4][4], bf[4][2];
#pragma unroll
        for (int mi = 0; mi < 4; mi++) {
            int mrow = warp_m + mi * 16 + lg;
            float2 p0 = *reinterpret_cast<const float2*>(&As[buf][mrow    ][kc    ]);
            float2 p1 = *reinterpret_cast<const float2*>(&As[buf][mrow + 8][kc    ]);
            float2 p2 = *reinterpret_cast<const float2*>(&As[buf][mrow    ][kc + 8]);
            float2 p3 = *reinterpret_cast<const float2*>(&As[buf][mrow + 8][kc + 8]);
            asm("cvt.rn.f16x2.f32 %0, %1, %2;" : "=r"(af[mi][0]) : "f"(p0.y), "f"(p0.x));
            asm("cvt.rn.f16x2.f32 %0, %1, %2;" : "=r"(af[mi][1]) : "f"(p1.y), "f"(p1.x));
            asm("cvt.rn.f16x2.f32 %0, %1, %2;" : "=r"(af[mi][2]) : "f"(p2.y), "f"(p2.x));
            asm("cvt.rn.f16x2.f32 %0, %1, %2;" : "=r"(af[mi][3]) : "f"(p3.y), "f"(p3.x));
        }
#pragma unroll
        for (int ni = 0; ni < 4; ni++) {
            int ncol = warp_n + ni * 8 + lg;
            bf[ni][0] = *reinterpret_cast<const uint32_t*>(&Bh[buf][ncol][kc    ]);
            bf[ni][1] = *reinterpret_cast<const uint32_t*>(&Bh[buf][ncol][kc + 8]);
        }
#pragma unroll
        for (int mi = 0; mi < 4; mi++)
#pragma unroll
            for (int ni = 0; ni < 4; ni++) {
                asm volatile(
                    "mma.sync.aligned.m16n8k16.row.col.f32.f16.f16.f32 "
                    "{%0,%1,%2,%3}, {%4,%5,%6,%7}, {%8,%9}, {%0,%1,%2,%3};"
                    : "+f"(c[mi][ni][0]), "+f"(c[mi][ni][1]),
                      "+f"(c[mi][ni][2]), "+f"(c[mi][ni][3])
                    : "r"(af[mi][0]), "r"(af[mi][1]), "r"(af[mi][2]), "r"(af[mi][3]),
                      "r"(bf[ni][0]), "r"(bf[ni][1]));
            }
        __syncthreads();
    }

#pragma unroll
    for (int mi = 0; mi < 4; mi++) {
#pragma unroll
        for (int ni = 0; ni < 4; ni++) {
            int r = row0 + warp_m + mi * 16 + lg;
            int cc = col0 + warp_n + ni * 8 + lq * 2;
            float bA = bias[cc], bB = bias[cc + 1];
            float v0 = fmaxf(c[mi][ni][0] + bA, 0.f);
            float v1 = fmaxf(c[mi][ni][1] + bB, 0.f);
            float v2 = fmaxf(c[mi][ni][2] + bA, 0.f);
            float v3 = fmaxf(c[mi][ni][3] + bB, 0.f);
            if (r < N)
                *reinterpret_cast<__half2*>(C16 + (size_t)r * M + cc) = __floats2half2_rn(v0, v1);
            if (r + 8 < N)
                *reinterpret_cast<__half2*>(C16 + (size_t)(r + 8) * M + cc) = __floats2half2_rn(v2, v3);
        }
    }
}

// ---------------- fp16 GEMM (enc2), BK=32, as in R8 ----------------
__global__ __launch_bounds__(256)
void fp16_gemm_kernel(const __half* __restrict__ A, const __half* __restrict__ BT,
                      const float* __restrict__ bias, __half* __restrict__ C16,
                      int N, int K, int M)
{
    const int BM = 128, BN = 128, BK = 32, PAD = 40;
    __shared__ alignas(16) __half Ah[2][BM][PAD];
    __shared__ alignas(16) __half Bh[2][BN][PAD];

    int tid = threadIdx.x;
    int wid = tid >> 5, lane = tid & 31;
    int warp_m = (wid & 1) * 64;
    int warp_n = (wid >> 1) * 32;
    int lq = lane & 3;
    int lg = lane >> 2;

    int row0 = blockIdx.y * BM;
    int col0 = blockIdx.x * BN;
    int nt = K / BK;

    float c[4][4][4];
#pragma unroll
    for (int mi = 0; mi < 4; mi++)
#pragma unroll
        for (int ni = 0; ni < 4; ni++)
#pragma unroll
            for (int r = 0; r < 4; r++) c[mi][ni][r] = 0.0f;

    auto loadTile = [&](int t, int buf) {
        int k0 = t * BK;
#pragma unroll
        for (int it = 0; it < 2; ++it) {
            int chunk = it * 256 + tid;
            int r = chunk >> 2, c8 = (chunk & 3) * 8;
            {
                int gm = row0 + r;
                const __half* src = A + (size_t)gm * K + k0 + c8;
                uint32_t dsh = (uint32_t)__cvta_generic_to_shared(&Ah[buf][r][c8]);
                int sz = (gm < N) ? 16 : 0;
                asm volatile("cp.async.cg.shared.global [%0], [%1], 16, %2;"
                             :: "r"(dsh), "l"(src), "r"(sz));
            }
            {
                int gn = col0 + r;
                const __half* src = BT + (size_t)gn * K + k0 + c8;
                uint32_t dsh = (uint32_t)__cvta_generic_to_shared(&Bh[buf][r][c8]);
                asm volatile("cp.async.cg.shared.global [%0], [%1], 16;"
                             :: "r"(dsh), "l"(src));
            }
        }
        asm volatile("cp.async.commit_group;");
    };

    loadTile(0, 0);
    for (int t = 0; t < nt; ++t) {
        int buf = t & 1;
        if (t + 1 < nt) {
            loadTile(t + 1, (t + 1) & 1);
            asm volatile("cp.async.wait_group 1;");
        } else {
            asm volatile("cp.async.wait_group 0;");
        }
        __syncthreads();

#pragma unroll
        for (int kk = 0; kk < BK; kk += 16) {
            int kc = kk + lq * 2;
            uint32_t af[4][4], bf[4][2];
#pragma unroll
            for (int mi = 0; mi < 4; mi++) {
                int mrow = warp_m + mi * 16 + lg;
                af[mi][0] = *reinterpret_cast<const uint32_t*>(&Ah[buf][mrow    ][kc    ]);
                af[mi][1] = *reinterpret_cast<const uint32_t*>(&Ah[buf][mrow + 8][kc    ]);
                af[mi][2] = *reinterpret_cast<const uint32_t*>(&Ah[buf][mrow    ][kc + 8]);
                af[mi][3] = *reinterpret_cast<const uint32_t*>(&Ah[buf][mrow + 8][kc + 8]);
            }
#pragma unroll
            for (int ni = 0; ni < 4; ni++) {
                int ncol = warp_n + ni * 8 + lg;
                bf[ni][0] = *reinterpret_cast<const uint32_t*>(&Bh[buf][ncol][kc    ]);
                bf[ni][1] = *reinterpret_cast<const uint32_t*>(&Bh[buf][ncol][kc + 8]);
            }
#pragma unroll
            for (int mi = 0; mi < 4; mi++)
#pragma unroll
                for (int ni = 0; ni < 4; ni++) {
                    asm volatile(
                        "mma.sync.aligned.m16n8k16.row.col.f32.f16.f16.f32 "
                        "{%0,%1,%2,%3}, {%4,%5,%6,%7}, {%8,%9}, {%0,%1,%2,%3};"
                        : "+f"(c[mi][ni][0]), "+f"(c[mi][ni][1]),
                          "+f"(c[mi][ni][2]), "+f"(c[mi][ni][3])
                        : "r"(af[mi][0]), "r"(af[mi][1]), "r"(af[mi][2]), "r"(af[mi][3]),
                          "r"(bf[ni][0]), "r"(bf[ni][1]));
                }
        }
        __syncthreads();
    }

#pragma unroll
    for (int mi = 0; mi < 4; mi++) {
#pragma unroll
        for (int ni = 0; ni < 4; ni++) {
            int r = row0 + warp_m + mi * 16 + lg;
            int cc = col0 + warp_n + ni * 8 + lq * 2;
            float v0 = c[mi][ni][0] + bias[cc];
            float v1 = c[mi][ni][1] + bias[cc + 1];
            float v2 = c[mi][ni][2] + bias[cc];
            float v3 = c[mi][ni][3] + bias[cc + 1];
            if (r < N)
                *reinterpret_cast<__half2*>(C16 + (size_t)r * M + cc) = __floats2half2_rn(v0, v1);
            if (r + 8 < N)
                *reinterpret_cast<__half2*>(C16 + (size_t)(r + 8) * M + cc) = __floats2half2_rn(v2, v3);
        }
    }
}

// ---------------- fused GCN layer: Z = agg(h) in smem -> h' = relu(Z@W + b) ----------------
__device__ __forceinline__ void accum_row(const __half2* hp, float w, float4& a0, float4& a1) {
    float2 f0 = __half22float2(hp[0]), f1 = __half22float2(hp[1]);
    float2 f2 = __half22float2(hp[2]), f3 = __half22float2(hp[3]);
    a0.x = fmaf(f0.x, w, a0.x); a0.y = fmaf(f0.y, w, a0.y);
    a0.z = fmaf(f1.x, w, a0.z); a0.w = fmaf(f1.y, w, a0.w);
    a1.x = fmaf(f2.x, w, a1.x); a1.y = fmaf(f2.y, w, a1.y);
    a1.z = fmaf(f3.x, w, a1.z); a1.w = fmaf(f3.y, w, a1.w);
}

__global__ __launch_bounds__(256, 2)
void fused_gcn_kernel(const __half* __restrict__ hin, const __half* __restrict__ WT,
                      const float* __restrict__ bias,
                      const float* __restrict__ dis,
                      const int* __restrict__ start, const int* __restrict__ csr_src,
                      __half* __restrict__ hout, float* __restrict__ meanOut, int n)
{
    extern __shared__ __align__(16) __half smem[];
    __half* Z  = smem;                      // [128][ZPAD]
    __half* Bh = smem + 128 * ZPAD;         // [2][128][BPAD]

    int tid = threadIdx.x;
    int wid = tid >> 5, lane = tid & 31;
    int nodeBase = blockIdx.x * 128;

    auto loadB = [&](int g, int buf) {      // g = nh*8 + kt
        int nh = g >> 3, kt = g & 7;
#pragma unroll
        for (int it = 0; it < 2; ++it) {
            int chunk = it * 256 + tid;     // 512 chunks of 16B
            int r = chunk >> 2, c8 = (chunk & 3) * 8;
            const __half* src = WT + (size_t)(nh * 128 + r) * H + kt * 32 + c8;
            uint32_t dsh = (uint32_t)__cvta_generic_to_shared(&Bh[(buf * 128 + r) * BPAD + c8]);
            asm volatile("cp.async.cg.shared.global [%0], [%1], 16;"
                         :: "r"(dsh), "l"(src));
        }
        asm volatile("cp.async.commit_group;");
    };
    loadB(0, 0);   // prefetch first W tile; completes during gather

    // ---- gather phase: warp w owns z-rows [w*16, w*16+16) ----
    for (int i = 0; i < 16; ++i) {
        int zrow = wid * 16 + i;
        int node = nodeBase + zrow;
        uint4 outw = make_uint4(0, 0, 0, 0);
        if (node < n) {
            float dd = dis[node];
            float self = dd * dd;
            uint4 us = *reinterpret_cast<const uint4*>(hin + (size_t)node * H + lane * 8);
            const __half2* hs = reinterpret_cast<const __half2*>(&us);
            float2 s0 = __half22float2(hs[0]), s1 = __half22float2(hs[1]);
            float2 s2 = __half22float2(hs[2]), s3 = __half22float2(hs[3]);
            float4 a0, a1;
            a0.x = s0.x * self; a0.y = s0.y * self;
            a0.z = s1.x * self; a0.w = s1.y * self;
            a1.x = s2.x * self; a1.y = s2.y * self;
            a1.z = s3.x * self; a1.w = s3.y * self;

            int j0 = start[node], j1 = start[node + 1];
            int j = j0;
            for (; j + 4 <= j1; j += 4) {
                int sA = csr_src[j], sB = csr_src[j + 1], sC = csr_src[j + 2], sD = csr_src[j + 3];
                float wA = dis[sA] * dd, wB = dis[sB] * dd, wC = dis[sC] * dd, wD = dis[sD] * dd;
                uint4 uA = *reinterpret_cast<const uint4*>(hin + (size_t)sA * H + lane * 8);
                uint4 uB = *reinterpret_cast<const uint4*>(hin + (size_t)sB * H + lane * 8);
                uint4 uC = *reinterpret_cast<const uint4*>(hin + (size_t)sC * H + lane * 8);
                uint4 uD = *reinterpret_cast<const uint4*>(hin + (size_t)sD * H + lane * 8);
                accum_row(reinterpret_cast<const __half2*>(&uA), wA, a0, a1);
                accum_row(reinterpret_cast<const __half2*>(&uB), wB, a0, a1);
                accum_row(reinterpret_cast<const __half2*>(&uC), wC, a0, a1);
                accum_row(reinterpret_cast<const __half2*>(&uD), wD, a0, a1);
            }
            for (; j < j1; ++j) {
                int s = csr_src[j];
                float w = dis[s] * dd;
                uint4 u = *reinterpret_cast<const uint4*>(hin + (size_t)s * H + lane * 8);
                accum_row(reinterpret_cast<const __half2*>(&u), w, a0, a1);
            }
            __half2* ho = reinterpret_cast<__half2*>(&outw);
            ho[0] = __floats2half2_rn(a0.x, a0.y);
            ho[1] = __floats2half2_rn(a0.z, a0.w);
            ho[2] = __floats2half2_rn(a1.x, a1.y);
            ho[3] = __floats2half2_rn(a1.z, a1.w);
        }
        *reinterpret_cast<uint4*>(Z + (size_t)zrow * ZPAD + lane * 8) = outw;
    }

    // ---- GEMM phase: h' tile [128 rows][256 cols], two 128-col halves ----
    int warp_m = (wid & 1) * 64;
    int warp_n = (wid >> 1) * 32;
    int lq = lane & 3;
    int lg = lane >> 2;

    for (int nh = 0; nh < 2; ++nh) {
        float c[4][4][4];
#pragma unroll
        for (int mi = 0; mi < 4; mi++)
#pragma unroll
            for (int ni = 0; ni < 4; ni++)
#pragma unroll
                for (int r = 0; r < 4; r++) c[mi][ni][r] = 0.0f;

        for (int kt = 0; kt < 8; ++kt) {
            int g = nh * 8 + kt;
            if (g + 1 < 16) {
                loadB(g + 1, (g + 1) & 1);
                asm volatile("cp.async.wait_group 1;");
            } else {
                asm volatile("cp.async.wait_group 0;");
            }
            __syncthreads();     // first iteration also fences gather Z writes
            int buf = g & 1;

#pragma unroll
            for (int kk = 0; kk < 32; kk += 16) {
                int kz = kt * 32 + kk + lq * 2;
                int kb = kk + lq * 2;
                uint32_t af[4][4], bf[4][2];
#pragma unroll
                for (int mi = 0; mi < 4; mi++) {
                    const __half* zp = Z + (size_t)(warp_m + mi * 16 + lg) * ZPAD + kz;
                    af[mi][0] = *reinterpret_cast<const uint32_t*>(zp);
                    af[mi][1] = *reinterpret_cast<const uint32_t*>(zp + 8 * ZPAD);
                    af[mi][2] = *reinterpret_cast<const uint32_t*>(zp + 8);
                    af[mi][3] = *reinterpret_cast<const uint32_t*>(zp + 8 * ZPAD + 8);
                }
#pragma unroll
                for (int ni = 0; ni < 4; ni++) {
                    const __half* bp = Bh + (size_t)(buf * 128 + warp_n + ni * 8 + lg) * BPAD + kb;
                    bf[ni][0] = *reinterpret_cast<const uint32_t*>(bp);
                    bf[ni][1] = *reinterpret_cast<const uint32_t*>(bp + 8);
                }
#pragma unroll
                for (int mi = 0; mi < 4; mi++)
#pragma unroll
                    for (int ni = 0; ni < 4; ni++) {
                        asm volatile(
                            "mma.sync.aligned.m16n8k16.row.col.f32.f16.f16.f32 "
                            "{%0,%1,%2,%3}, {%4,%5,%6,%7}, {%8,%9}, {%0,%1,%2,%3};"
                            : "+f"(c[mi][ni][0]), "+f"(c[mi][ni][1]),
                              "+f"(c[mi][ni][2]), "+f"(c[mi][ni][3])
                            : "r"(af[mi][0]), "r"(af[mi][1]), "r"(af[mi][2]), "r"(af[mi][3]),
                              "r"(bf[ni][0]), "r"(bf[ni][1]));
                    }
            }
            __syncthreads();
        }

        // ---- epilogue for this half ----
        if (meanOut) {
            float colA[4] = {0, 0, 0, 0}, colB[4] = {0, 0, 0, 0};
#pragma unroll
            for (int mi = 0; mi < 4; mi++) {
                int r = nodeBase + warp_m + mi * 16 + lg;
#pragma unroll
                for (int ni = 0; ni < 4; ni++) {
                    int cc = nh * 128 + warp_n + ni * 8 + lq * 2;
                    float bA = bias[cc], bB = bias[cc + 1];
                    float v0 = fmaxf(c[mi][ni][0] + bA, 0.f);
                    float v1 = fmaxf(c[mi][ni][1] + bB, 0.f);
                    float v2 = fmaxf(c[mi][ni][2] + bA, 0.f);
                    float v3 = fmaxf(c[mi][ni][3] + bB, 0.f);
                    if (r >= n)     { v0 = 0.f; v1 = 0.f; }
                    if (r + 8 >= n) { v2 = 0.f; v3 = 0.f; }
                    colA[ni] += v0 + v2;
                    colB[ni] += v1 + v3;
                }
            }
#pragma unroll
            for (int ni = 0; ni < 4; ni++) {
                float sA = colA[ni], sB = colB[ni];
                sA += __shfl_down_sync(0xffffffff, sA, 16);
                sA += __shfl_down_sync(0xffffffff, sA, 8);
                sA += __shfl_down_sync(0xffffffff, sA, 4);
                sB += __shfl_down_sync(0xffffffff, sB, 16);
                sB += __shfl_down_sync(0xffffffff, sB, 8);
                sB += __shfl_down_sync(0xffffffff, sB, 4);
                if (lg == 0) {
                    int cc = nh * 128 + warp_n + ni * 8 + lq * 2;
                    atomicAdd(&meanOut[cc],     sA);
                    atomicAdd(&meanOut[cc + 1], sB);
                }
            }
        } else {
#pragma unroll
            for (int mi = 0; mi < 4; mi++) {
#pragma unroll
                for (int ni = 0; ni < 4; ni++) {
                    int r = nodeBase + warp_m + mi * 16 + lg;
                    int cc = nh * 128 + warp_n + ni * 8 + lq * 2;
                    float bA = bias[cc], bB = bias[cc + 1];
                    float v0 = fmaxf(c[mi][ni][0] + bA, 0.f);
                    float v1 = fmaxf(c[mi][ni][1] + bB, 0.f);
                    float v2 = fmaxf(c[mi][ni][2] + bA, 0.f);
                    float v3 = fmaxf(c[mi][ni][3] + bB, 0.f);
                    if (r < n)
                        *reinterpret_cast<__half2*>(hout + (size_t)r * H + cc) = __floats2half2_rn(v0, v1);
                    if (r + 8 < n)
                        *reinterpret_cast<__half2*>(hout + (size_t)(r + 8) * H + cc) = __floats2half2_rn(v2, v3);
                }
            }
        }
    }
}

// ---------------- head MLP ----------------
__global__ void head_kernel(const float* __restrict__ mean,
                            const float* __restrict__ W1, const float* __restrict__ b1,
                            const float* __restrict__ W2, const float* __restrict__ b2,
                            float* __restrict__ out, float invN)
{
    __shared__ float g[H];
    __shared__ float t[D_OUT];
    int tid = threadIdx.x;
    g[tid]       = mean[tid]       * invN;
    g[tid + 128] = mean[tid + 128] * invN;
    __syncthreads();
    float acc = b1[tid];
    for (int k = 0; k < H; k++) acc = fmaf(g[k], W1[k * D_OUT + tid], acc);
    t[tid] = fmaxf(acc, 0.0f);
    __syncthreads();
    float acc2 = b2[tid];
    for (int k = 0; k < D_OUT; k++) acc2 = fmaf(t[k], W2[k * D_OUT + tid], acc2);
    out[tid] = acc2;
}

// ---------------- launch ----------------
extern "C" void kernel_launch(void* const* d_in, const int* in_sizes, int n_in,
                              void* d_out, int out_size)
{
    const float* x       = (const float*)d_in[0];
    const int*   eidx    = (const int*)  d_in[1];
    const float* W_enc1  = (const float*)d_in[3];
    const float* b_enc1  = (const float*)d_in[4];
    const float* W_enc2  = (const float*)d_in[5];
    const float* b_enc2  = (const float*)d_in[6];
    const float* W_g[3]  = { (const float*)d_in[8],  (const float*)d_in[10], (const float*)d_in[12] };
    const float* b_g[3]  = { (const float*)d_in[9],  (const float*)d_in[11], (const float*)d_in[13] };
    const float* W_h1    = (const float*)d_in[14];
    const float* b_h1    = (const float*)d_in[15];
    const float* W_h2    = (const float*)d_in[16];
    const float* b_h2    = (const float*)d_in[17];

    const int n = in_sizes[0] / D_IN;       // 50000
    const int E = in_sizes[2];              // 1600000
    const int* src = eidx;
    const int* dst = eidx + E;

    __half *p_h16, *p_hwA, *p_w16;
    float *p_dis, *p_mean;
    int *p_deg, *p_start, *p_cursor, *p_csr, *p_bsum, *p_boff;
    cudaGetSymbolAddress((void**)&p_h16,    g_h16);
    cudaGetSymbolAddress((void**)&p_hwA,    g_hwA);
    cudaGetSymbolAddress((void**)&p_w16,    g_w16);
    cudaGetSymbolAddress((void**)&p_dis,    g_dis);
    cudaGetSymbolAddress((void**)&p_deg,    g_deg);
    cudaGetSymbolAddress((void**)&p_start,  g_start);
    cudaGetSymbolAddress((void**)&p_cursor, g_cursor);
    cudaGetSymbolAddress((void**)&p_csr,    g_csr_src);
    cudaGetSymbolAddress((void**)&p_bsum,   g_bsum);
    cudaGetSymbolAddress((void**)&p_boff,   g_boff);
    cudaGetSymbolAddress((void**)&p_mean,   g_mean);

    __half* WT_enc1 = p_w16;                         // [H][D_INP]
    __half* WT_sq   = p_w16 + (size_t)H * D_INP;     // 4 x [H][H]

    static cudaStream_t s2 = nullptr, s3 = nullptr;
    static cudaEvent_t evFork = nullptr, evCsr = nullptr, evW = nullptr;
    static bool attrSet = false;
    if (!s2) {
        cudaStreamCreateWithFlags(&s2, cudaStreamNonBlocking);
        cudaStreamCreateWithFlags(&s3, cudaStreamNonBlocking);
        cudaEventCreateWithFlags(&evFork, cudaEventDisableTiming);
        cudaEventCreateWithFlags(&evCsr,  cudaEventDisableTiming);
        cudaEventCreateWithFlags(&evW,    cudaEventDisableTiming);
    }
    if (!attrSet) {
        cudaFuncSetAttribute(fused_gcn_kernel,
                             cudaFuncAttributeMaxDynamicSharedMemorySize, FUSED_SMEM);
        attrSet = true;
    }

    // ---- fork ----
    cudaEventRecord(evFork, 0);
    cudaStreamWaitEvent(s2, evFork, 0);
    cudaStreamWaitEvent(s3, evFork, 0);

    // s2: CSR chain (hides under encoder)
    cudaMemsetAsync(p_deg, 0, n * sizeof(int), s2);
    deg_kernel<<<(E + 255) / 256, 256, 0, s2>>>(dst, p_deg, E);
    dis_kernel<<<(n + 255) / 256, 256, 0, s2>>>(p_deg, p_dis, n);
    const int nScanBlocks = (n + 1023) / 1024;
    scan_block_kernel<<<nScanBlocks, 1024, 0, s2>>>(p_deg, p_start, p_bsum, n);
    scan_sums_kernel<<<1, 64, 0, s2>>>(p_bsum, p_boff, nScanBlocks);
    scan_finalize_kernel<<<(n + 255) / 256, 256, 0, s2>>>(p_deg, p_start, p_boff, p_cursor, n);
    fill_csr_kernel<<<(E + 255) / 256, 256, 0, s2>>>(src, dst, p_cursor, p_csr, E);
    cudaEventRecord(evCsr, s2);

    // s3: weight conversions
    wtrans_kernel<<<(H * D_INP + 255) / 256, 256, 0, s3>>>(W_enc1, WT_enc1, D_IN, H, D_INP);
    const float* wsrc[4] = { W_enc2, W_g[0], W_g[1], W_g[2] };
    for (int i = 0; i < 4; ++i)
        wtrans_kernel<<<(H * H + 255) / 256, 256, 0, s3>>>(wsrc[i], WT_sq + (size_t)i * H * H, H, H, H);
    cudaEventRecord(evW, s3);

    // s0: mean clear + encoder
    cudaMemsetAsync(p_mean, 0, H * sizeof(float), 0);
    cudaStreamWaitEvent(0, evW, 0);

    dim3 gemmBlock(256);
    dim3 gemmGrid(H / 128, (n + 127) / 128);

    enc1_gemm_kernel<<<gemmGrid, gemmBlock>>>(x, WT_enc1, b_enc1, p_hwA, n, D_IN, D_INP, H);
    fp16_gemm_kernel<<<gemmGrid, gemmBlock>>>(p_hwA, WT_sq + 0 * H * H, b_enc2, p_h16, n, H, H);

    // ---- join CSR, then 3 fused GCN layers ----
    cudaStreamWaitEvent(0, evCsr, 0);

    const int fBlocks = (n + 127) / 128;
    fused_gcn_kernel<<<fBlocks, 256, FUSED_SMEM>>>(p_h16, WT_sq + 1 * H * H, b_g[0],
                                                   p_dis, p_start, p_csr, p_hwA, nullptr, n);
    fused_gcn_kernel<<<fBlocks, 256, FUSED_SMEM>>>(p_hwA, WT_sq + 2 * H * H, b_g[1],
                                                   p_dis, p_start, p_csr, p_h16, nullptr, n);
    fused_gcn_kernel<<<fBlocks, 256, FUSED_SMEM>>>(p_h16, WT_sq + 3 * H * H, b_g[2],
                                                   p_dis, p_start, p_csr, nullptr, p_mean, n);

    head_kernel<<<1, D_OUT>>>(p_mean, W_h1, b_h1, W_h2, b_h2, (float*)d_out, 1.0f / (float)n);
}

// round 10
// speedup vs baseline: 1.2324x; 1.2324x over previous
#include <cuda_runtime.h>
#include <cuda_fp16.h>
#include <cuda_bf16.h>
#include <cstdint>

#define NODES_MAX 50000
#define EDGES_MAX 1600000
#define H 256
#define D_IN 518
#define D_INP 544
#define D_OUT 128

// ---------------- device scratch ----------------
__device__ __half g_h16  [NODES_MAX * H];
__device__ __half g_hwA  [NODES_MAX * H];
__device__ __half g_hwB  [NODES_MAX * H];
__device__ __half g_w16  [H * D_INP + 4 * H * H];
__device__ float  g_dis[NODES_MAX];
__device__ int    g_deg[NODES_MAX];
__device__ int    g_start[NODES_MAX + 1];
__device__ int    g_cursor[NODES_MAX];
__device__ int    g_csr_src[EDGES_MAX];
__device__ int    g_bsum[64];
__device__ int    g_boff[64];
__device__ float  g_mean[H];

// ---------------- weight transpose + fp16 ----------------
__global__ void wtrans_kernel(const float* __restrict__ W, __half* __restrict__ WT,
                              int K, int M, int Kp) {
    int idx = blockIdx.x * blockDim.x + threadIdx.x;
    if (idx >= M * Kp) return;
    int m = idx / Kp, k = idx % Kp;
    float v = (k < K) ? W[(size_t)k * M + m] : 0.0f;
    WT[idx] = __float2half_rn(v);
}

// ---------------- degree / normalization ----------------
__global__ void deg_kernel(const int* __restrict__ dst, int* __restrict__ deg, int E) {
    int i = blockIdx.x * blockDim.x + threadIdx.x;
    if (i < E) atomicAdd(&deg[dst[i]], 1);
}

__global__ void dis_kernel(const int* __restrict__ deg, float* __restrict__ dis, int n) {
    int i = blockIdx.x * blockDim.x + threadIdx.x;
    if (i < n) dis[i] = rsqrtf(1.0f + (float)deg[i]);
}

// ---------------- parallel scan (3 phases) ----------------
__global__ void scan_block_kernel(const int* __restrict__ deg, int* __restrict__ start,
                                  int* __restrict__ bsum, int n)
{
    __shared__ int warpSums[32];
    int i = blockIdx.x * 1024 + threadIdx.x;
    int lane = threadIdx.x & 31, warp = threadIdx.x >> 5;
    int v = (i < n) ? deg[i] : 0;
    int inc = v;
#pragma unroll
    for (int off = 1; off < 32; off <<= 1) {
        int t = __shfl_up_sync(0xffffffff, inc, off);
        if (lane >= off) inc += t;
    }
    if (lane == 31) warpSums[warp] = inc;
    __syncthreads();
    if (warp == 0) {
        int s = warpSums[lane];
#pragma unroll
        for (int off = 1; off < 32; off <<= 1) {
            int t = __shfl_up_sync(0xffffffff, s, off);
            if (lane >= off) s += t;
        }
        warpSums[lane] = s;
    }
    __syncthreads();
    int add = (warp > 0) ? warpSums[warp - 1] : 0;
    inc += add;
    if (i < n) start[i + 1] = inc;
    if (threadIdx.x == 1023) bsum[blockIdx.x] = inc;
}

__global__ void scan_sums_kernel(const int* __restrict__ bsum, int* __restrict__ boff, int nb) {
    int lane = threadIdx.x;
    int v = (lane < nb) ? bsum[lane] : 0;
    __shared__ int s[64];
    s[lane] = v;
    __syncthreads();
    for (int off = 1; off < 64; off <<= 1) {
        int t = (lane >= off) ? s[lane - off] : 0;
        __syncthreads();
        s[lane] += t;
        __syncthreads();
    }
    if (lane < nb) boff[lane] = (lane > 0) ? s[lane - 1] : 0;
}

__global__ void scan_finalize_kernel(const int* __restrict__ deg, int* __restrict__ start,
                                     const int* __restrict__ boff, int* __restrict__ cursor, int n)
{
    int i = blockIdx.x * blockDim.x + threadIdx.x;
    if (i < n) {
        int s = start[i + 1] + boff[i >> 10];
        start[i + 1] = s;
        cursor[i] = s - deg[i];
        if (i == 0) start[0] = 0;
    }
}

__global__ void fill_csr_kernel(const int* __restrict__ src, const int* __restrict__ dst,
                                int* __restrict__ cursor, int* __restrict__ csr_src, int E)
{
    int e = blockIdx.x * blockDim.x + threadIdx.x;
    if (e < E) {
        int d = dst[e];
        int p = atomicAdd(&cursor[d], 1);
        csr_src[p] = src[e];
    }
}

// ---------------- enc1: fp32-A x fp16-B GEMM (8B A loads), relu ----------------
__global__ __launch_bounds__(256)
void enc1_gemm_kernel(const float* __restrict__ A, const __half* __restrict__ BT,
                      const float* __restrict__ bias, __half* __restrict__ C16,
                      int N, int K, int Kp, int M)
{
    const int BM = 128, BN = 128, BK = 16, PK = 20, PB = 24;
    __shared__ float As[2][BM][PK];
    __shared__ alignas(16) __half Bh[2][BN][PB];

    int tid = threadIdx.x;
    int wid = tid >> 5, lane = tid & 31;
    int warp_m = (wid & 1) * 64;
    int warp_n = (wid >> 1) * 32;
    int lq = lane & 3;
    int lg = lane >> 2;

    int row0 = blockIdx.y * BM;
    int col0 = blockIdx.x * BN;
    int nt = Kp / BK;

    float c[4][4][4];
#pragma unroll
    for (int mi = 0; mi < 4; mi++)
#pragma unroll
        for (int ni = 0; ni < 4; ni++)
#pragma unroll
            for (int r = 0; r < 4; r++) c[mi][ni][r] = 0.0f;

    int bRow = tid >> 1;
    int bCol = (tid & 1) * 8;

    auto loadTile = [&](int t, int buf) {
        int k0 = t * BK;
#pragma unroll
        for (int it = 0; it < 4; ++it) {
            int idx = it * 256 + tid;             // 1024 chunks of 8B
            int m = idx >> 3, kp = (idx & 7) * 2;
            int gm = row0 + m, gk = k0 + kp;
            const float* src = A + (size_t)gm * K + gk;
            uint32_t dsh = (uint32_t)__cvta_generic_to_shared(&As[buf][m][kp]);
            int sz = (gm < N && gk < K) ? 8 : 0;  // K even -> pair fully in range
            asm volatile("cp.async.ca.shared.global [%0], [%1], 8, %2;"
                         :: "r"(dsh), "l"(src), "r"(sz));
        }
        {
            const __half* src = BT + (size_t)(col0 + bRow) * Kp + k0 + bCol;
            uint32_t dsh = (uint32_t)__cvta_generic_to_shared(&Bh[buf][bRow][bCol]);
            asm volatile("cp.async.cg.shared.global [%0], [%1], 16;"
                         :: "r"(dsh), "l"(src));
        }
        asm volatile("cp.async.commit_group;");
    };

    loadTile(0, 0);
    for (int t = 0; t < nt; ++t) {
        int buf = t & 1;
        if (t + 1 < nt) {
            loadTile(t + 1, (t + 1) & 1);
            asm volatile("cp.async.wait_group 1;");
        } else {
            asm volatile("cp.async.wait_group 0;");
        }
        __syncthreads();

        int kc = lq * 2;
        uint32_t af[4][4], bf[4][2];
#pragma unroll
        for (int mi = 0; mi < 4; mi++) {
            int mrow = warp_m + mi * 16 + lg;
            float2 p0 = *reinterpret_cast<const float2*>(&As[buf][mrow    ][kc    ]);
            float2 p1 = *reinterpret_cast<const float2*>(&As[buf][mrow + 8][kc    ]);
            float2 p2 = *reinterpret_cast<const float2*>(&As[buf][mrow    ][kc + 8]);
            float2 p3 = *reinterpret_cast<const float2*>(&As[buf][mrow + 8][kc + 8]);
            asm("cvt.rn.f16x2.f32 %0, %1, %2;" : "=r"(af[mi][0]) : "f"(p0.y), "f"(p0.x));
            asm("cvt.rn.f16x2.f32 %0, %1, %2;" : "=r"(af[mi][1]) : "f"(p1.y), "f"(p1.x));
            asm("cvt.rn.f16x2.f32 %0, %1, %2;" : "=r"(af[mi][2]) : "f"(p2.y), "f"(p2.x));
            asm("cvt.rn.f16x2.f32 %0, %1, %2;" : "=r"(af[mi][3]) : "f"(p3.y), "f"(p3.x));
        }
#pragma unroll
        for (int ni = 0; ni < 4; ni++) {
            int ncol = warp_n + ni * 8 + lg;
            bf[ni][0] = *reinterpret_cast<const uint32_t*>(&Bh[buf][ncol][kc    ]);
            bf[ni][1] = *reinterpret_cast<const uint32_t*>(&Bh[buf][ncol][kc + 8]);
        }
#pragma unroll
        for (int mi = 0; mi < 4; mi++)
#pragma unroll
            for (int ni = 0; ni < 4; ni++) {
                asm volatile(
                    "mma.sync.aligned.m16n8k16.row.col.f32.f16.f16.f32 "
                    "{%0,%1,%2,%3}, {%4,%5,%6,%7}, {%8,%9}, {%0,%1,%2,%3};"
                    : "+f"(c[mi][ni][0]), "+f"(c[mi][ni][1]),
                      "+f"(c[mi][ni][2]), "+f"(c[mi][ni][3])
                    : "r"(af[mi][0]), "r"(af[mi][1]), "r"(af[mi][2]), "r"(af[mi][3]),
                      "r"(bf[ni][0]), "r"(bf[ni][1]));
            }
        __syncthreads();
    }

#pragma unroll
    for (int mi = 0; mi < 4; mi++) {
#pragma unroll
        for (int ni = 0; ni < 4; ni++) {
            int r = row0 + warp_m + mi * 16 + lg;
            int cc = col0 + warp_n + ni * 8 + lq * 2;
            float bA = bias[cc], bB = bias[cc + 1];
            float v0 = fmaxf(c[mi][ni][0] + bA, 0.f);
            float v1 = fmaxf(c[mi][ni][1] + bB, 0.f);
            float v2 = fmaxf(c[mi][ni][2] + bA, 0.f);
            float v3 = fmaxf(c[mi][ni][3] + bB, 0.f);
            if (r < N)
                *reinterpret_cast<__half2*>(C16 + (size_t)r * M + cc) = __floats2half2_rn(v0, v1);
            if (r + 8 < N)
                *reinterpret_cast<__half2*>(C16 + (size_t)(r + 8) * M + cc) = __floats2half2_rn(v2, v3);
        }
    }
}

// ---------------- fp16 tensor-core GEMM, BK=32, cp.async double-buffered ----------------
__global__ __launch_bounds__(256)
void fp16_gemm_kernel(const __half* __restrict__ A, const __half* __restrict__ BT,
                      const float* __restrict__ bias, __half* __restrict__ C16,
                      int N, int K, int M)
{
    const int BM = 128, BN = 128, BK = 32, PAD = 40;
    __shared__ alignas(16) __half Ah[2][BM][PAD];
    __shared__ alignas(16) __half Bh[2][BN][PAD];

    int tid = threadIdx.x;
    int wid = tid >> 5, lane = tid & 31;
    int warp_m = (wid & 1) * 64;
    int warp_n = (wid >> 1) * 32;
    int lq = lane & 3;
    int lg = lane >> 2;

    int row0 = blockIdx.y * BM;
    int col0 = blockIdx.x * BN;
    int nt = K / BK;

    float c[4][4][4];
#pragma unroll
    for (int mi = 0; mi < 4; mi++)
#pragma unroll
        for (int ni = 0; ni < 4; ni++)
#pragma unroll
            for (int r = 0; r < 4; r++) c[mi][ni][r] = 0.0f;

    auto loadTile = [&](int t, int buf) {
        int k0 = t * BK;
#pragma unroll
        for (int it = 0; it < 2; ++it) {
            int chunk = it * 256 + tid;
            int r = chunk >> 2, c8 = (chunk & 3) * 8;
            {
                int gm = row0 + r;
                const __half* src = A + (size_t)gm * K + k0 + c8;
                uint32_t dsh = (uint32_t)__cvta_generic_to_shared(&Ah[buf][r][c8]);
                int sz = (gm < N) ? 16 : 0;
                asm volatile("cp.async.cg.shared.global [%0], [%1], 16, %2;"
                             :: "r"(dsh), "l"(src), "r"(sz));
            }
            {
                int gn = col0 + r;
                const __half* src = BT + (size_t)gn * K + k0 + c8;
                uint32_t dsh = (uint32_t)__cvta_generic_to_shared(&Bh[buf][r][c8]);
                asm volatile("cp.async.cg.shared.global [%0], [%1], 16;"
                             :: "r"(dsh), "l"(src));
            }
        }
        asm volatile("cp.async.commit_group;");
    };

    loadTile(0, 0);
    for (int t = 0; t < nt; ++t) {
        int buf = t & 1;
        if (t + 1 < nt) {
            loadTile(t + 1, (t + 1) & 1);
            asm volatile("cp.async.wait_group 1;");
        } else {
            asm volatile("cp.async.wait_group 0;");
        }
        __syncthreads();

#pragma unroll
        for (int kk = 0; kk < BK; kk += 16) {
            int kc = kk + lq * 2;
            uint32_t af[4][4], bf[4][2];
#pragma unroll
            for (int mi = 0; mi < 4; mi++) {
                int mrow = warp_m + mi * 16 + lg;
                af[mi][0] = *reinterpret_cast<const uint32_t*>(&Ah[buf][mrow    ][kc    ]);
                af[mi][1] = *reinterpret_cast<const uint32_t*>(&Ah[buf][mrow + 8][kc    ]);
                af[mi][2] = *reinterpret_cast<const uint32_t*>(&Ah[buf][mrow    ][kc + 8]);
                af[mi][3] = *reinterpret_cast<const uint32_t*>(&Ah[buf][mrow + 8][kc + 8]);
            }
#pragma unroll
            for (int ni = 0; ni < 4; ni++) {
                int ncol = warp_n + ni * 8 + lg;
                bf[ni][0] = *reinterpret_cast<const uint32_t*>(&Bh[buf][ncol][kc    ]);
                bf[ni][1] = *reinterpret_cast<const uint32_t*>(&Bh[buf][ncol][kc + 8]);
            }
#pragma unroll
            for (int mi = 0; mi < 4; mi++)
#pragma unroll
                for (int ni = 0; ni < 4; ni++) {
                    asm volatile(
                        "mma.sync.aligned.m16n8k16.row.col.f32.f16.f16.f32 "
                        "{%0,%1,%2,%3}, {%4,%5,%6,%7}, {%8,%9}, {%0,%1,%2,%3};"
                        : "+f"(c[mi][ni][0]), "+f"(c[mi][ni][1]),
                          "+f"(c[mi][ni][2]), "+f"(c[mi][ni][3])
                        : "r"(af[mi][0]), "r"(af[mi][1]), "r"(af[mi][2]), "r"(af[mi][3]),
                          "r"(bf[ni][0]), "r"(bf[ni][1]));
                }
        }
        __syncthreads();
    }

#pragma unroll
    for (int mi = 0; mi < 4; mi++) {
#pragma unroll
        for (int ni = 0; ni < 4; ni++) {
            int r = row0 + warp_m + mi * 16 + lg;
            int cc = col0 + warp_n + ni * 8 + lq * 2;
            float v0 = c[mi][ni][0], v1 = c[mi][ni][1];
            float v2 = c[mi][ni][2], v3 = c[mi][ni][3];
            if (bias) {
                float bA = bias[cc], bB = bias[cc + 1];
                v0 += bA; v1 += bB; v2 += bA; v3 += bB;
            }
            if (r < N)
                *reinterpret_cast<__half2*>(C16 + (size_t)r * M + cc) = __floats2half2_rn(v0, v1);
            if (r + 8 < N)
                *reinterpret_cast<__half2*>(C16 + (size_t)(r + 8) * M + cc) = __floats2half2_rn(v2, v3);
        }
    }
}

// ---------------- fused GCN aggregation (+ optional mean), node-range version ----------------
__device__ __forceinline__ void accum_row(const __half2* hp, float w, float4& a0, float4& a1) {
    float2 f0 = __half22float2(hp[0]), f1 = __half22float2(hp[1]);
    float2 f2 = __half22float2(hp[2]), f3 = __half22float2(hp[3]);
    a0.x = fmaf(f0.x, w, a0.x); a0.y = fmaf(f0.y, w, a0.y);
    a0.z = fmaf(f1.x, w, a0.z); a0.w = fmaf(f1.y, w, a0.w);
    a1.x = fmaf(f2.x, w, a1.x); a1.y = fmaf(f2.y, w, a1.y);
    a1.z = fmaf(f3.x, w, a1.z); a1.w = fmaf(f3.y, w, a1.w);
}

__global__ __launch_bounds__(256)
void gather_kernel(const __half* __restrict__ hw16,
                   const float* __restrict__ dis, const float* __restrict__ b,
                   const int* __restrict__ start, const int* __restrict__ csr_src,
                   __half* __restrict__ hout16, float* __restrict__ meanOut,
                   int node0, int nNodes)
{
    __shared__ float ms[H];
    int warp = (blockIdx.x * blockDim.x + threadIdx.x) >> 5;
    int lane = threadIdx.x & 31;
    int node = node0 + warp;
    bool active = warp < nNodes;

    if (meanOut) {
        if (threadIdx.x < H) ms[threadIdx.x] = 0.0f;
        __syncthreads();
    }

    float4 a0 = make_float4(0, 0, 0, 0), a1 = make_float4(0, 0, 0, 0);

    if (active) {
        float dd = dis[node];
        float self = dd * dd;

        uint4 us = *reinterpret_cast<const uint4*>(hw16 + (size_t)node * H + lane * 8);
        const __half2* hs = reinterpret_cast<const __half2*>(&us);
        const float4* bb = reinterpret_cast<const float4*>(b);
        float4 b0 = bb[lane * 2 + 0];
        float4 b1 = bb[lane * 2 + 1];
        float2 s0 = __half22float2(hs[0]), s1 = __half22float2(hs[1]);
        float2 s2 = __half22float2(hs[2]), s3 = __half22float2(hs[3]);

        a0.x = fmaf(s0.x, self, b0.x); a0.y = fmaf(s0.y, self, b0.y);
        a0.z = fmaf(s1.x, self, b0.z); a0.w = fmaf(s1.y, self, b0.w);
        a1.x = fmaf(s2.x, self, b1.x); a1.y = fmaf(s2.y, self, b1.y);
        a1.z = fmaf(s3.x, self, b1.z); a1.w = fmaf(s3.y, self, b1.w);

        int j0 = start[node], j1 = start[node + 1];

        int j = j0;
        for (; j + 4 <= j1; j += 4) {
            int sA = csr_src[j], sB = csr_src[j + 1], sC = csr_src[j + 2], sD = csr_src[j + 3];
            float wA = dis[sA] * dd, wB = dis[sB] * dd, wC = dis[sC] * dd, wD = dis[sD] * dd;
            uint4 uA = *reinterpret_cast<const uint4*>(hw16 + (size_t)sA * H + lane * 8);
            uint4 uB = *reinterpret_cast<const uint4*>(hw16 + (size_t)sB * H + lane * 8);
            uint4 uC = *reinterpret_cast<const uint4*>(hw16 + (size_t)sC * H + lane * 8);
            uint4 uD = *reinterpret_cast<const uint4*>(hw16 + (size_t)sD * H + lane * 8);
            accum_row(reinterpret_cast<const __half2*>(&uA), wA, a0, a1);
            accum_row(reinterpret_cast<const __half2*>(&uB), wB, a0, a1);
            accum_row(reinterpret_cast<const __half2*>(&uC), wC, a0, a1);
            accum_row(reinterpret_cast<const __half2*>(&uD), wD, a0, a1);
        }
        for (; j < j1; ++j) {
            int s = csr_src[j];
            float w = dis[s] * dd;
            uint4 u = *reinterpret_cast<const uint4*>(hw16 + (size_t)s * H + lane * 8);
            accum_row(reinterpret_cast<const __half2*>(&u), w, a0, a1);
        }

        a0.x = fmaxf(a0.x, 0.f); a0.y = fmaxf(a0.y, 0.f);
        a0.z = fmaxf(a0.z, 0.f); a0.w = fmaxf(a0.w, 0.f);
        a1.x = fmaxf(a1.x, 0.f); a1.y = fmaxf(a1.y, 0.f);
        a1.z = fmaxf(a1.z, 0.f); a1.w = fmaxf(a1.w, 0.f);

        uint4 outw;
        __half2* ho = reinterpret_cast<__half2*>(&outw);
        ho[0] = __floats2half2_rn(a0.x, a0.y);
        ho[1] = __floats2half2_rn(a0.z, a0.w);
        ho[2] = __floats2half2_rn(a1.x, a1.y);
        ho[3] = __floats2half2_rn(a1.z, a1.w);
        *reinterpret_cast<uint4*>(hout16 + (size_t)node * H + lane * 8) = outw;
    }

    if (meanOut) {
        if (active) {
            int base = lane * 8;
            atomicAdd(&ms[base + 0], __half2float(__float2half_rn(a0.x)));
            atomicAdd(&ms[base + 1], __half2float(__float2half_rn(a0.y)));
            atomicAdd(&ms[base + 2], __half2float(__float2half_rn(a0.z)));
            atomicAdd(&ms[base + 3], __half2float(__float2half_rn(a0.w)));
            atomicAdd(&ms[base + 4], __half2float(__float2half_rn(a1.x)));
            atomicAdd(&ms[base + 5], __half2float(__float2half_rn(a1.y)));
            atomicAdd(&ms[base + 6], __half2float(__float2half_rn(a1.z)));
            atomicAdd(&ms[base + 7], __half2float(__float2half_rn(a1.w)));
        }
        __syncthreads();
        if (threadIdx.x < H) atomicAdd(&meanOut[threadIdx.x], ms[threadIdx.x]);
    }
}

// ---------------- head MLP ----------------
__global__ void head_kernel(const float* __restrict__ mean,
                            const float* __restrict__ W1, const float* __restrict__ b1,
                            const float* __restrict__ W2, const float* __restrict__ b2,
                            float* __restrict__ out, float invN)
{
    __shared__ float g[H];
    __shared__ float t[D_OUT];
    int tid = threadIdx.x;
    g[tid]       = mean[tid]       * invN;
    g[tid + 128] = mean[tid + 128] * invN;
    __syncthreads();
    float acc = b1[tid];
    for (int k = 0; k < H; k++) acc = fmaf(g[k], W1[k * D_OUT + tid], acc);
    t[tid] = fmaxf(acc, 0.0f);
    __syncthreads();
    float acc2 = b2[tid];
    for (int k = 0; k < D_OUT; k++) acc2 = fmaf(t[k], W2[k * D_OUT + tid], acc2);
    out[tid] = acc2;
}

// ---------------- launch ----------------
extern "C" void kernel_launch(void* const* d_in, const int* in_sizes, int n_in,
                              void* d_out, int out_size)
{
    const float* x       = (const float*)d_in[0];
    const int*   eidx    = (const int*)  d_in[1];
    const float* W_enc1  = (const float*)d_in[3];
    const float* b_enc1  = (const float*)d_in[4];
    const float* W_enc2  = (const float*)d_in[5];
    const float* b_enc2  = (const float*)d_in[6];
    const float* W_g[3]  = { (const float*)d_in[8],  (const float*)d_in[10], (const float*)d_in[12] };
    const float* b_g[3]  = { (const float*)d_in[9],  (const float*)d_in[11], (const float*)d_in[13] };
    const float* W_h1    = (const float*)d_in[14];
    const float* b_h1    = (const float*)d_in[15];
    const float* W_h2    = (const float*)d_in[16];
    const float* b_h2    = (const float*)d_in[17];

    const int n = in_sizes[0] / D_IN;       // 50000
    const int E = in_sizes[2];              // 1600000
    const int* src = eidx;
    const int* dst = eidx + E;

    __half *p_h16, *p_hwA, *p_hwB, *p_w16;
    float *p_dis, *p_mean;
    int *p_deg, *p_start, *p_cursor, *p_csr, *p_bsum, *p_boff;
    cudaGetSymbolAddress((void**)&p_h16,    g_h16);
    cudaGetSymbolAddress((void**)&p_hwA,    g_hwA);
    cudaGetSymbolAddress((void**)&p_hwB,    g_hwB);
    cudaGetSymbolAddress((void**)&p_w16,    g_w16);
    cudaGetSymbolAddress((void**)&p_dis,    g_dis);
    cudaGetSymbolAddress((void**)&p_deg,    g_deg);
    cudaGetSymbolAddress((void**)&p_start,  g_start);
    cudaGetSymbolAddress((void**)&p_cursor, g_cursor);
    cudaGetSymbolAddress((void**)&p_csr,    g_csr_src);
    cudaGetSymbolAddress((void**)&p_bsum,   g_bsum);
    cudaGetSymbolAddress((void**)&p_boff,   g_boff);
    cudaGetSymbolAddress((void**)&p_mean,   g_mean);

    __half* WT_enc1 = p_w16;                         // [H][D_INP]
    __half* WT_sq   = p_w16 + (size_t)H * D_INP;     // 4 x [H][H]

    static cudaStream_t s2 = nullptr, s3 = nullptr;
    static cudaEvent_t evFork = nullptr, evCsr = nullptr, evW = nullptr;
    static cudaEvent_t evG1a = nullptr, evM2a = nullptr, evG2a = nullptr, evM3a = nullptr;
    if (!s2) {
        cudaStreamCreateWithFlags(&s2, cudaStreamNonBlocking);
        cudaStreamCreateWithFlags(&s3, cudaStreamNonBlocking);
        cudaEventCreateWithFlags(&evFork, cudaEventDisableTiming);
        cudaEventCreateWithFlags(&evCsr,  cudaEventDisableTiming);
        cudaEventCreateWithFlags(&evW,    cudaEventDisableTiming);
        cudaEventCreateWithFlags(&evG1a,  cudaEventDisableTiming);
        cudaEventCreateWithFlags(&evM2a,  cudaEventDisableTiming);
        cudaEventCreateWithFlags(&evG2a,  cudaEventDisableTiming);
        cudaEventCreateWithFlags(&evM3a,  cudaEventDisableTiming);
    }

    // ---- fork ----
    cudaEventRecord(evFork, 0);
    cudaStreamWaitEvent(s2, evFork, 0);
    cudaStreamWaitEvent(s3, evFork, 0);

    // s2: CSR chain
    cudaMemsetAsync(p_deg, 0, n * sizeof(int), s2);
    deg_kernel<<<(E + 255) / 256, 256, 0, s2>>>(dst, p_deg, E);
    dis_kernel<<<(n + 255) / 256, 256, 0, s2>>>(p_deg, p_dis, n);
    const int nScanBlocks = (n + 1023) / 1024;
    scan_block_kernel<<<nScanBlocks, 1024, 0, s2>>>(p_deg, p_start, p_bsum, n);
    scan_sums_kernel<<<1, 64, 0, s2>>>(p_bsum, p_boff, nScanBlocks);
    scan_finalize_kernel<<<(n + 255) / 256, 256, 0, s2>>>(p_deg, p_start, p_boff, p_cursor, n);
    fill_csr_kernel<<<(E + 255) / 256, 256, 0, s2>>>(src, dst, p_cursor, p_csr, E);
    cudaEventRecord(evCsr, s2);

    // s3: weight conversions
    wtrans_kernel<<<(H * D_INP + 255) / 256, 256, 0, s3>>>(W_enc1, WT_enc1, D_IN, H, D_INP);
    const float* wsrc[4] = { W_enc2, W_g[0], W_g[1], W_g[2] };
    for (int i = 0; i < 4; ++i)
        wtrans_kernel<<<(H * H + 255) / 256, 256, 0, s3>>>(wsrc[i], WT_sq + (size_t)i * H * H, H, H, H);
    cudaEventRecord(evW, s3);

    // s0: mean clear + encoder chain
    cudaMemsetAsync(p_mean, 0, H * sizeof(float), 0);
    cudaStreamWaitEvent(0, evW, 0);

    dim3 gemmBlock(256);
    dim3 gemmGridFull(H / 128, (n + 127) / 128);

    enc1_gemm_kernel<<<gemmGridFull, gemmBlock>>>(x, WT_enc1, b_enc1, p_hwA, n, D_IN, D_INP, H);
    fp16_gemm_kernel<<<gemmGridFull, gemmBlock>>>(p_hwA, WT_sq + 0 * H * H, b_enc2, p_h16, n, H, H);
    fp16_gemm_kernel<<<gemmGridFull, gemmBlock>>>(p_h16, WT_sq + 1 * H * H, nullptr, p_hwA, n, H, H);

    // ---- join CSR, then split-pipelined GCN layers ----
    cudaStreamWaitEvent(0, evCsr, 0);

    const int n2 = 25088;                 // 128-aligned split
    const int rowsB = n - n2;             // 24912
    dim3 gridHalfA(H / 128, n2 / 128);
    dim3 gridHalfB(H / 128, (rowsB + 127) / 128);
    const int gBlocksA = (n2 + 7) / 8;
    const int gBlocksB = (rowsB + 7) / 8;
    const int gBlocksFull = (n + 7) / 8;

    // layer 1: gather from hwA -> h16 (split); GEMM g2 -> hwB
    gather_kernel<<<gBlocksA, 256>>>(p_hwA, p_dis, b_g[0], p_start, p_csr, p_h16, nullptr, 0, n2);
    cudaEventRecord(evG1a, 0);
    cudaStreamWaitEvent(s2, evG1a, 0);
    fp16_gemm_kernel<<<gridHalfA, gemmBlock, 0, s2>>>(p_h16, WT_sq + 2 * H * H, nullptr, p_hwB, n2, H, H);
    cudaEventRecord(evM2a, s2);
    gather_kernel<<<gBlocksB, 256>>>(p_hwA, p_dis, b_g[0], p_start, p_csr, p_h16, nullptr, n2, rowsB);
    fp16_gemm_kernel<<<gridHalfB, gemmBlock>>>(p_h16 + (size_t)n2 * H, WT_sq + 2 * H * H, nullptr,
                                               p_hwB + (size_t)n2 * H, rowsB, H, H);
    cudaStreamWaitEvent(0, evM2a, 0);

    // layer 2: gather from hwB -> h16 (split); GEMM g3 -> hwA
    gather_kernel<<<gBlocksA, 256>>>(p_hwB, p_dis, b_g[1], p_start, p_csr, p_h16, nullptr, 0, n2);
    cudaEventRecord(evG2a, 0);
    cudaStreamWaitEvent(s2, evG2a, 0);
    fp16_gemm_kernel<<<gridHalfA, gemmBlock, 0, s2>>>(p_h16, WT_sq + 3 * H * H, nullptr, p_hwA, n2, H, H);
    cudaEventRecord(evM3a, s2);
    gather_kernel<<<gBlocksB, 256>>>(p_hwB, p_dis, b_g[1], p_start, p_csr, p_h16, nullptr, n2, rowsB);
    fp16_gemm_kernel<<<gridHalfB, gemmBlock>>>(p_h16 + (size_t)n2 * H, WT_sq + 3 * H * H, nullptr,
                                               p_hwA + (size_t)n2 * H, rowsB, H, H);
    cudaStreamWaitEvent(0, evM3a, 0);

    // layer 3: full gather from hwA (+fused mean)
    gather_kernel<<<gBlocksFull, 256>>>(p_hwA, p_dis, b_g[2], p_start, p_csr, p_h16, p_mean, 0, n);

    head_kernel<<<1, D_OUT>>>(p_mean, W_h1, b_h1, W_h2, b_h2, (float*)d_out, 1.0f / (float)n);
}